// round 15
// baseline (speedup 1.0000x reference)
#include <cuda_runtime.h>

#define FDIM  128
#define F4    32             // FDIM/4
#define BMAX  2048
#define NMAX  1100000
#define NSORT 296            // persistent CTAs (2/SM, exactly one wave)
#define TILE  2048           // idx staging tile (rows)
#define NW    16             // warps per CTA
#define GMAX  8              // max nodes per thread in sort phase (296*512*8 > NMAX)
#define EPSC  1e-3f

// ---- scratch (device globals; no allocations allowed) ----
__device__ int      g_counts[BMAX];      // per-graph totals (zeroed in-kernel for replay)
__device__ int      g_offsets[BMAX + 1]; // per-graph base offsets
__device__ int      g_perm[NMAX];        // node ids sorted by graph
__device__ unsigned g_bar0, g_bar1, g_bar2;  // monotonic epoch barrier counters

__global__ __launch_bounds__(512, 2)
void gn_all_kernel(const void*  __restrict__ gid,
                   const float* __restrict__ values,
                   const float* __restrict__ gamma,
                   const float* __restrict__ beta,
                   const float* __restrict__ alpha,
                   float*       __restrict__ out,
                   int N, int B) {
    __shared__ int      sh[BMAX];        // hist -> warp totals -> scatter cursors
    __shared__ int      sbase[BMAX];     // this CTA's within-graph base
    __shared__ int      idx[TILE];
    __shared__ float    ss[NW * FDIM];
    __shared__ float    sq[NW * FDIM];
    __shared__ float    scs[FDIM];
    __shared__ float    shs[FDIM];
    __shared__ int      s_is64;
    __shared__ unsigned s_epoch;

    int t    = threadIdx.x;
    int cta  = blockIdx.x;
    int lane = t & 31;
    int w    = t >> 5;

    // ================= sort phase A: probe + convert + histogram =================
    for (int i = t; i < B; i += 512) sh[i] = 0;
    if (t == 0) s_is64 = 1;
    __syncthreads();

    int chunk = (N + NSORT - 1) / NSORT;
    int s = cta * chunk;
    int e = s + chunk; if (e > N) e = N;

    {   // local probe: view chunk as int64; any out-of-range value -> int32
        int probe = (e - s) / 2;
        if (probe > 512) probe = 512;
        const long long* g64 = (const long long*)gid + (s / 2);
        if (t < probe) {
            long long v = g64[t];
            if (v < 0 || v >= (long long)B) s_is64 = 0;
        }
    }
    __syncthreads();
    int is64 = s_is64;

    int gr[GMAX];                        // register-resident converted gids
#pragma unroll
    for (int it = 0; it < GMAX; it++) {
        int i = s + t + it * 512;
        int g = -1;
        if (i < e) {
            g = is64 ? (int)((const long long*)gid)[i] : ((const int*)gid)[i];
            g = (g < 0) ? 0 : (g >= B ? B - 1 : g);
            atomicAdd(&sh[g], 1);
        }
        gr[it] = g;
    }
    __syncthreads();

    // within-graph base for this CTA via global atomic (order-free prefix)
    for (int i = t; i < B; i += 512) {
        int cnt = sh[i];
        sbase[i] = cnt ? atomicAdd(&g_counts[i], cnt) : 0;
    }

    // barrier 0 (epoch): arrive; derive this replay's epoch from the ticket
    __syncthreads();
    __threadfence();
    if (t == 0) {
        unsigned old = atomicAdd(&g_bar0, 1u);
        s_epoch = old / NSORT + 1u;
    }
    __syncthreads();
    unsigned epoch = s_epoch;

    // ========== sort phase B: CTA0 waits, shuffle-scans counts -> offsets ==========
    if (cta == 0) {
        if (t == 0) {
            while (atomicAdd(&g_bar0, 0u) < epoch * NSORT) __nanosleep(64);
        }
        __syncthreads();
        int base = t * 4;                // 512 thr x 4 = 2048
        int v0 = (base + 0 < B) ? __ldcg(&g_counts[base + 0]) : 0;
        int v1 = (base + 1 < B) ? __ldcg(&g_counts[base + 1]) : 0;
        int v2 = (base + 2 < B) ? __ldcg(&g_counts[base + 2]) : 0;
        int v3 = (base + 3 < B) ? __ldcg(&g_counts[base + 3]) : 0;
        int tsum = v0 + v1 + v2 + v3;
        int inc  = tsum;                 // warp-inclusive scan of thread sums
        for (int off = 1; off < 32; off <<= 1) {
            int n = __shfl_up_sync(0xFFFFFFFFu, inc, off);
            if (lane >= off) inc += n;
        }
        if (lane == 31) sh[w] = inc;     // 16 warp totals
        __syncthreads();
        if (w == 0) {
            int wv = (lane < 16) ? sh[lane] : 0;
            int wi = wv;
            for (int off = 1; off < 32; off <<= 1) {
                int n = __shfl_up_sync(0xFFFFFFFFu, wi, off);
                if (lane >= off) wi += n;
            }
            if (lane < 16) sh[lane] = wi - wv;   // exclusive warp bases
        }
        __syncthreads();
        int excl = sh[w] + (inc - tsum); // exclusive prefix for this thread
        g_offsets[base + 0] = excl;
        g_offsets[base + 1] = excl + v0;
        g_offsets[base + 2] = excl + v0 + v1;
        g_offsets[base + 3] = excl + v0 + v1 + v2;
        if (t == 511) g_offsets[BMAX] = excl + tsum;
        __syncthreads();
        __threadfence();
        if (t == 0) atomicAdd(&g_bar1, 1u);      // publish offsets
    } else {
        if (t == 0) {
            while (atomicAdd(&g_bar1, 0u) < epoch) __nanosleep(64);
        }
        __syncthreads();
    }

    // ============ sort phase C: scatter with smem cursors, gids in regs ============
    for (int i = t; i < B; i += 512)
        sh[i] = __ldcg(&g_offsets[i]) + sbase[i];
    __syncthreads();
#pragma unroll
    for (int it = 0; it < GMAX; it++) {
        int i = s + t + it * 512;
        int g = gr[it];
        if (g >= 0) {
            int pos = atomicAdd(&sh[g], 1);
            g_perm[pos] = i;
        }
    }

    // zero g_counts for the next replay (offsets already published; counts dead)
    {
        int zi = cta * 512 + t;
        if (zi < B) g_counts[zi] = 0;
    }

    // barrier 2 (epoch): all perm writes visible before the fused phase reads
    __syncthreads();
    __threadfence();
    if (t == 0) {
        atomicAdd(&g_bar2, 1u);
        while (atomicAdd(&g_bar2, 0u) < epoch * NSORT) __nanosleep(64);
    }
    __syncthreads();

    // ================= fused phase: stats + normalize, R10 body =================
    // graphs cta, cta+NSORT, ... : 296 concurrent graphs x 250KB = 74MB in L2.
    const float4* v4 = (const float4*)values;
    float4*       o4 = (float4*)out;

    for (int b = cta; b < B; b += NSORT) {
        int start = g_offsets[b];
        int end   = g_offsets[b + 1];
        int c     = end - start;
        if (c == 0) continue;            // uniform per CTA

        float4 sv = make_float4(0.f, 0.f, 0.f, 0.f);
        float4 qv = make_float4(0.f, 0.f, 0.f, 0.f);

        // ---- loop1: gather + moments (2 independent rows in flight per warp) ----
        for (int ts = start; ts < end; ts += TILE) {
            int tn = end - ts; if (tn > TILE) tn = TILE;
            __syncthreads();
            for (int i = t; i < tn; i += 512) idx[i] = g_perm[ts + i];
            __syncthreads();
            int r = w;
            for (; r + NW < tn; r += 2 * NW) {
                float4 va = __ldg(&v4[(size_t)idx[r]      * F4 + lane]);
                float4 vb = __ldg(&v4[(size_t)idx[r + NW] * F4 + lane]);
                sv.x += va.x; sv.y += va.y; sv.z += va.z; sv.w += va.w;
                qv.x = fmaf(va.x, va.x, qv.x);
                qv.y = fmaf(va.y, va.y, qv.y);
                qv.z = fmaf(va.z, va.z, qv.z);
                qv.w = fmaf(va.w, va.w, qv.w);
                sv.x += vb.x; sv.y += vb.y; sv.z += vb.z; sv.w += vb.w;
                qv.x = fmaf(vb.x, vb.x, qv.x);
                qv.y = fmaf(vb.y, vb.y, qv.y);
                qv.z = fmaf(vb.z, vb.z, qv.z);
                qv.w = fmaf(vb.w, vb.w, qv.w);
            }
            if (r < tn) {
                float4 v = __ldg(&v4[(size_t)idx[r] * F4 + lane]);
                sv.x += v.x; sv.y += v.y; sv.z += v.z; sv.w += v.w;
                qv.x = fmaf(v.x, v.x, qv.x);
                qv.y = fmaf(v.y, v.y, qv.y);
                qv.z = fmaf(v.z, v.z, qv.z);
                qv.w = fmaf(v.w, v.w, qv.w);
            }
        }

        ((float4*)ss)[w * F4 + lane] = sv;
        ((float4*)sq)[w * F4 + lane] = qv;
        __syncthreads();

        // ---- reduce NW partials, compute scale/shift ----
        if (t < FDIM) {
            float S = 0.f, Q = 0.f;
#pragma unroll
            for (int i = 0; i < NW; i++) {
                S += ss[i * FDIM + t];
                Q += sq[i * FDIM + t];
            }
            float inv  = 1.0f / (float)c;
            float m    = S * inv;
            float m2   = Q * inv;
            float msh  = m * alpha[t];                    // shifted mean
            float var  = m2 - 2.0f * msh * m + msh * msh; // E[(x - msh)^2]
            float rstd = rsqrtf(var + EPSC);
            float sc   = gamma[t] * rstd;
            scs[t] = sc;
            shs[t] = beta[t] - msh * sc;
        }
        __syncthreads();

        float4 sc4 = ((const float4*)scs)[lane];
        float4 sh4 = ((const float4*)shs)[lane];

        // ---- loop2: normalize. Reads: L2 hits (evict-on-use). Writes: streaming. ----
        for (int ts = start; ts < end; ts += TILE) {
            int tn = end - ts; if (tn > TILE) tn = TILE;
            if (c > TILE) {                 // re-stage only if >1 tile
                __syncthreads();
                for (int i = t; i < tn; i += 512) idx[i] = g_perm[ts + i];
                __syncthreads();
            }
            int r = w;
            for (; r + NW < tn; r += 2 * NW) {
                size_t ga = (size_t)idx[r]      * F4 + lane;
                size_t gb = (size_t)idx[r + NW] * F4 + lane;
                float4 va = __ldcs(&v4[ga]);
                float4 vb = __ldcs(&v4[gb]);
                float4 oa, ob;
                oa.x = fmaf(va.x, sc4.x, sh4.x);
                oa.y = fmaf(va.y, sc4.y, sh4.y);
                oa.z = fmaf(va.z, sc4.z, sh4.z);
                oa.w = fmaf(va.w, sc4.w, sh4.w);
                ob.x = fmaf(vb.x, sc4.x, sh4.x);
                ob.y = fmaf(vb.y, sc4.y, sh4.y);
                ob.z = fmaf(vb.z, sc4.z, sh4.z);
                ob.w = fmaf(vb.w, sc4.w, sh4.w);
                __stcs(&o4[ga], oa);
                __stcs(&o4[gb], ob);
            }
            if (r < tn) {
                size_t gi = (size_t)idx[r] * F4 + lane;
                float4 v  = __ldcs(&v4[gi]);
                float4 o;
                o.x = fmaf(v.x, sc4.x, sh4.x);
                o.y = fmaf(v.y, sc4.y, sh4.y);
                o.z = fmaf(v.z, sc4.z, sh4.z);
                o.w = fmaf(v.w, sc4.w, sh4.w);
                __stcs(&o4[gi], o);
            }
        }
        __syncthreads();   // idx stable before next graph's staging
    }
}

extern "C" void kernel_launch(void* const* d_in, const int* in_sizes, int n_in,
                              void* d_out, int out_size) {
    const float* values = (const float*)d_in[0];
    const void*  gid    = d_in[1];
    // d_in[2] = reference_ids (only its length B is needed)
    const float* gamma  = (const float*)d_in[3];
    const float* beta   = (const float*)d_in[4];
    const float* alpha  = (const float*)d_in[5];

    int N = in_sizes[0] / FDIM;
    int B = in_sizes[2];
    if (B > BMAX) B = BMAX;
    if (B < 1)    B = 1;

    gn_all_kernel<<<NSORT, 512>>>(gid, values, gamma, beta, alpha,
                                  (float*)d_out, N, B);
}

// round 16
// speedup vs baseline: 1.0347x; 1.0347x over previous
#include <cuda_runtime.h>

#define FDIM  128
#define F4    32             // FDIM/4
#define BMAX  2048
#define NMAX  1100000
#define NCTA  296            // sort CTAs (2/SM, one wave — co-residency proven in R15)
#define TILE  2048           // idx staging tile (rows)
#define NW    16             // warps per fused CTA
#define GMAX  8              // max nodes per sort thread (296*512*8 > NMAX)
#define EPSC  1e-3f

// ---- scratch (device globals; no allocations allowed) ----
__device__ int g_counts[BMAX];           // per-graph totals (atomic; reset by fused)
__device__ int g_offsets[BMAX + 1];      // per-graph base offsets
__device__ int g_perm[NMAX];             // node ids sorted by graph
__device__ int g_bar0;                   // arrive counter (reset by fused)

// ---- sort kernel: hist+atomic-prefix -> redundant scan -> scatter ----
// 296 CTAs x 512 thr (2/SM). One grid barrier only: after it, every CTA
// scans g_counts itself (smem-local result), so no publish/poll round trip.
__global__ __launch_bounds__(512, 2) void gn_sort_kernel(const void* __restrict__ gid,
                                                         int N, int B) {
    __shared__ int sh[BMAX];      // hist -> exclusive prefix -> scatter cursors
    __shared__ int sbase[BMAX];   // this CTA's within-graph base
    __shared__ int wsum[16];      // warp totals for the scan
    __shared__ int s_is64;
    int t    = threadIdx.x;
    int cta  = blockIdx.x;
    int lane = t & 31;
    int w    = t >> 5;

    // ---- phase A: dtype probe + convert + per-CTA histogram ----
    for (int i = t; i < B; i += 512) sh[i] = 0;
    if (t == 0) s_is64 = 1;
    __syncthreads();

    int chunk = (N + NCTA - 1) / NCTA;
    int s = cta * chunk;
    int e = s + chunk; if (e > N) e = N;

    {   // local probe: view chunk as int64; any out-of-range value -> int32
        int probe = (e - s) / 2;
        if (probe > 512) probe = 512;
        const long long* g64 = (const long long*)gid + (s / 2);
        if (t < probe) {
            long long v = g64[t];
            if (v < 0 || v >= (long long)B) s_is64 = 0;
        }
    }
    __syncthreads();
    int is64 = s_is64;

    int gr[GMAX];                 // register-resident converted gids
#pragma unroll
    for (int it = 0; it < GMAX; it++) {
        int i = s + t + it * 512;
        int g = -1;
        if (i < e) {
            g = is64 ? (int)((const long long*)gid)[i] : ((const int*)gid)[i];
            g = (g < 0) ? 0 : (g >= B ? B - 1 : g);
            atomicAdd(&sh[g], 1);
        }
        gr[it] = g;
    }
    __syncthreads();

    // within-graph base for this CTA via global atomic (order-free prefix)
    for (int i = t; i < B; i += 512) {
        int cnt = sh[i];
        sbase[i] = cnt ? atomicAdd(&g_counts[i], cnt) : 0;
    }

    // grid barrier: ALL CTAs wait until every CTA's counts are in
    __syncthreads();
    __threadfence();
    if (t == 0) {
        atomicAdd(&g_bar0, 1);
        while (atomicAdd(&g_bar0, 0) < NCTA) __nanosleep(64);
    }
    __syncthreads();

    // ---- phase B: every CTA redundantly scans counts (smem-local result) ----
    int base = t * 4;                // 512 thr x 4 = 2048
    int v0 = (base + 0 < B) ? __ldcg(&g_counts[base + 0]) : 0;
    int v1 = (base + 1 < B) ? __ldcg(&g_counts[base + 1]) : 0;
    int v2 = (base + 2 < B) ? __ldcg(&g_counts[base + 2]) : 0;
    int v3 = (base + 3 < B) ? __ldcg(&g_counts[base + 3]) : 0;
    int tsum = v0 + v1 + v2 + v3;
    int inc  = tsum;                 // warp-inclusive scan of thread sums
    for (int off = 1; off < 32; off <<= 1) {
        int n = __shfl_up_sync(0xFFFFFFFFu, inc, off);
        if (lane >= off) inc += n;
    }
    if (lane == 31) wsum[w] = inc;   // 16 warp totals
    __syncthreads();
    if (w == 0) {
        int wv = (lane < 16) ? wsum[lane] : 0;
        int wi = wv;
        for (int off = 1; off < 32; off <<= 1) {
            int n = __shfl_up_sync(0xFFFFFFFFu, wi, off);
            if (lane >= off) wi += n;
        }
        if (lane < 16) wsum[lane] = wi - wv;     // exclusive warp bases
    }
    __syncthreads();
    int excl = wsum[w] + (inc - tsum);           // exclusive prefix @ base

    // scatter cursors: exclusive prefix + this CTA's base (sh hist is dead)
    sh[base + 0] = excl                + sbase[base + 0];
    sh[base + 1] = excl + v0           + sbase[base + 1];
    sh[base + 2] = excl + v0 + v1      + sbase[base + 2];
    sh[base + 3] = excl + v0 + v1 + v2 + sbase[base + 3];

    // CTA0 additionally publishes g_offsets for the fused launch
    if (cta == 0) {
        g_offsets[base + 0] = excl;
        g_offsets[base + 1] = excl + v0;
        g_offsets[base + 2] = excl + v0 + v1;
        g_offsets[base + 3] = excl + v0 + v1 + v2;
        if (t == 511) g_offsets[BMAX] = excl + tsum;
    }
    __syncthreads();

    // ---- phase C: scatter with smem cursors, gids from registers ----
#pragma unroll
    for (int it = 0; it < GMAX; it++) {
        int i = s + t + it * 512;
        int g = gr[it];
        if (g >= 0) {
            int pos = atomicAdd(&sh[g], 1);
            g_perm[pos] = i;
        }
    }
}

// ---- FUSED stats + normalize (R10/R12/R14 committed config — converged).
// 1 CTA (512 thr / 16 warps) per graph, 2 CTAs/SM. loop1 __ldg populates L2
// (296 x 250KB = 74MB < 126MB); loop2 __ldcs re-reads from L2, __stcs
// streaming stores avoid write-allocate pollution. Resets sort scratch for
// the next replay (stream-ordered after the sort kernel finished).
__global__ __launch_bounds__(512, 2) void gn_fused_kernel(const float* __restrict__ values,
                                                          const float* __restrict__ gamma,
                                                          const float* __restrict__ beta,
                                                          const float* __restrict__ alpha,
                                                          float* __restrict__ out,
                                                          int B) {
    __shared__ int   idx[TILE];
    __shared__ float ss[NW * FDIM];   // per-warp partial sums
    __shared__ float sq[NW * FDIM];   // per-warp partial sumsq
    __shared__ float scs[FDIM];
    __shared__ float shs[FDIM];

    if (blockIdx.x == 0) {            // reset sort scratch for next replay
        if (threadIdx.x == 0) g_bar0 = 0;
        for (int i = threadIdx.x; i < B; i += 512) g_counts[i] = 0;
    }

    int b     = blockIdx.x;
    int start = g_offsets[b];
    int end   = g_offsets[b + 1];
    int c     = end - start;
    if (c == 0) return;                 // uniform per CTA

    int w    = threadIdx.x >> 5;        // 0..15
    int lane = threadIdx.x & 31;

    const float4* v4 = (const float4*)values;
    float4*       o4 = (float4*)out;

    float4 s = make_float4(0.f, 0.f, 0.f, 0.f);
    float4 q = make_float4(0.f, 0.f, 0.f, 0.f);

    // ---- loop1: gather + moments (2 independent rows in flight per warp) ----
    for (int ts = start; ts < end; ts += TILE) {
        int tn = end - ts; if (tn > TILE) tn = TILE;
        __syncthreads();
        for (int i = threadIdx.x; i < tn; i += 512) idx[i] = g_perm[ts + i];
        __syncthreads();
        int r = w;
        for (; r + NW < tn; r += 2 * NW) {
            float4 va = __ldg(&v4[(size_t)idx[r]      * F4 + lane]);
            float4 vb = __ldg(&v4[(size_t)idx[r + NW] * F4 + lane]);
            s.x += va.x; s.y += va.y; s.z += va.z; s.w += va.w;
            q.x = fmaf(va.x, va.x, q.x);
            q.y = fmaf(va.y, va.y, q.y);
            q.z = fmaf(va.z, va.z, q.z);
            q.w = fmaf(va.w, va.w, q.w);
            s.x += vb.x; s.y += vb.y; s.z += vb.z; s.w += vb.w;
            q.x = fmaf(vb.x, vb.x, q.x);
            q.y = fmaf(vb.y, vb.y, q.y);
            q.z = fmaf(vb.z, vb.z, q.z);
            q.w = fmaf(vb.w, vb.w, q.w);
        }
        if (r < tn) {
            float4 v = __ldg(&v4[(size_t)idx[r] * F4 + lane]);
            s.x += v.x; s.y += v.y; s.z += v.z; s.w += v.w;
            q.x = fmaf(v.x, v.x, q.x);
            q.y = fmaf(v.y, v.y, q.y);
            q.z = fmaf(v.z, v.z, q.z);
            q.w = fmaf(v.w, v.w, q.w);
        }
    }

    ((float4*)ss)[w * F4 + lane] = s;
    ((float4*)sq)[w * F4 + lane] = q;
    __syncthreads();

    // ---- reduce NW partials, compute scale/shift ----
    int f = threadIdx.x;
    if (f < FDIM) {
        float S = 0.f, Q = 0.f;
#pragma unroll
        for (int i = 0; i < NW; i++) {
            S += ss[i * FDIM + f];
            Q += sq[i * FDIM + f];
        }
        float inv  = 1.0f / (float)c;
        float m    = S * inv;
        float m2   = Q * inv;
        float msh  = m * alpha[f];                    // shifted mean
        float var  = m2 - 2.0f * msh * m + msh * msh; // E[(x - msh)^2]
        float rstd = rsqrtf(var + EPSC);
        float sc   = gamma[f] * rstd;
        scs[f] = sc;
        shs[f] = beta[f] - msh * sc;
    }
    __syncthreads();

    float4 sc4 = ((const float4*)scs)[lane];
    float4 sh4 = ((const float4*)shs)[lane];

    // ---- loop2: normalize. Reads: L2 hits, evict-on-use. Writes: streaming. ----
    for (int ts = start; ts < end; ts += TILE) {
        int tn = end - ts; if (tn > TILE) tn = TILE;
        if (c > TILE) {                     // re-stage only if >1 tile
            __syncthreads();
            for (int i = threadIdx.x; i < tn; i += 512) idx[i] = g_perm[ts + i];
            __syncthreads();
        }
        int r = w;
        for (; r + NW < tn; r += 2 * NW) {
            size_t ga = (size_t)idx[r]      * F4 + lane;
            size_t gb = (size_t)idx[r + NW] * F4 + lane;
            float4 va = __ldcs(&v4[ga]);
            float4 vb = __ldcs(&v4[gb]);
            float4 oa, ob;
            oa.x = fmaf(va.x, sc4.x, sh4.x);
            oa.y = fmaf(va.y, sc4.y, sh4.y);
            oa.z = fmaf(va.z, sc4.z, sh4.z);
            oa.w = fmaf(va.w, sc4.w, sh4.w);
            ob.x = fmaf(vb.x, sc4.x, sh4.x);
            ob.y = fmaf(vb.y, sc4.y, sh4.y);
            ob.z = fmaf(vb.z, sc4.z, sh4.z);
            ob.w = fmaf(vb.w, sc4.w, sh4.w);
            __stcs(&o4[ga], oa);
            __stcs(&o4[gb], ob);
        }
        if (r < tn) {
            size_t gi = (size_t)idx[r] * F4 + lane;
            float4 v  = __ldcs(&v4[gi]);
            float4 o;
            o.x = fmaf(v.x, sc4.x, sh4.x);
            o.y = fmaf(v.y, sc4.y, sh4.y);
            o.z = fmaf(v.z, sc4.z, sh4.z);
            o.w = fmaf(v.w, sc4.w, sh4.w);
            __stcs(&o4[gi], o);
        }
    }
}

extern "C" void kernel_launch(void* const* d_in, const int* in_sizes, int n_in,
                              void* d_out, int out_size) {
    const float* values = (const float*)d_in[0];
    const void*  gid    = d_in[1];
    // d_in[2] = reference_ids (only its length B is needed)
    const float* gamma  = (const float*)d_in[3];
    const float* beta   = (const float*)d_in[4];
    const float* alpha  = (const float*)d_in[5];

    int N = in_sizes[0] / FDIM;
    int B = in_sizes[2];
    if (B > BMAX) B = BMAX;
    if (B < 1)    B = 1;

    gn_sort_kernel<<<NCTA, 512>>>(gid, N, B);
    gn_fused_kernel<<<B, 512>>>(values, gamma, beta, alpha, (float*)d_out, B);
}